// round 15
// baseline (speedup 1.0000x reference)
#include <cuda_runtime.h>
#include <cstdint>

#define NN 50000
#define HH 128
#define EE 800000
#define AA 16
#define TT 4
#define SORT_CAP (EE + 128*TT)

// ---------------- device scratch ----------------
__device__ float g_msg[NN*HH];
__device__ int   g_sorted[SORT_CAP];
__device__ int   g_count[TT];
__device__ int   g_cursor[TT];
__device__ int   g_padTotal;
__device__ float g_wT[2*HH*3*HH];      // GRU weights transposed k-major, tf32-rounded
__device__ float g_w1r[TT*144*HH];     // tf32-rounded W1
__device__ float g_w2r[TT*HH*HH];      // tf32-rounded W2

// ---------------- helpers ----------------
__device__ __forceinline__ float tf32r(float x) {
    uint32_t u;
    asm("cvt.rna.tf32.f32 %0, %1;" : "=r"(u) : "f"(x));
    return __uint_as_float(u);
}

#define MMA_TF32(d, a, b) \
    asm volatile("mma.sync.aligned.m16n8k8.row.col.f32.tf32.tf32.f32 " \
        "{%0,%1,%2,%3}, {%4,%5,%6,%7}, {%8,%9}, {%0,%1,%2,%3};" \
        : "+f"((d)[0]), "+f"((d)[1]), "+f"((d)[2]), "+f"((d)[3]) \
        : "r"(__float_as_uint((a)[0])), "r"(__float_as_uint((a)[1])), \
          "r"(__float_as_uint((a)[2])), "r"(__float_as_uint((a)[3])), \
          "r"(__float_as_uint((b)[0])), "r"(__float_as_uint((b)[1])))

// ---------------- prep kernels ----------------
__global__ void zero_counts_kernel() { if (threadIdx.x < TT) g_count[threadIdx.x] = 0; }

__global__ void zero_msg_kernel() {
    const int n4 = NN*HH/4;
    for (int i = blockIdx.x*blockDim.x + threadIdx.x; i < n4; i += gridDim.x*blockDim.x)
        ((float4*)g_msg)[i] = make_float4(0.f,0.f,0.f,0.f);
}

__global__ void fill_sorted_kernel() {
    for (int i = blockIdx.x*blockDim.x + threadIdx.x; i < SORT_CAP; i += gridDim.x*blockDim.x)
        g_sorted[i] = -1;
}

__global__ void hist_kernel(const int* __restrict__ et) {
    const int lane = threadIdx.x & 31;
    for (int i = blockIdx.x*blockDim.x + threadIdx.x; i < EE; i += gridDim.x*blockDim.x) {
        int t = et[i];
        unsigned am = __activemask();
        unsigned m = __match_any_sync(am, t);
        int leader = __ffs(m) - 1;
        if (lane == leader) atomicAdd(&g_count[t], __popc(m));
    }
}

__global__ void scan_kernel() {
    if (threadIdx.x == 0 && blockIdx.x == 0) {
        int po = 0;
        for (int t = 0; t < TT; ++t) {
            g_cursor[t] = po;
            po += (g_count[t] + 127) & ~127;
        }
        g_padTotal = po;
    }
}

__global__ void scatter_kernel(const int* __restrict__ et) {
    const int lane = threadIdx.x & 31;
    for (int i = blockIdx.x*blockDim.x + threadIdx.x; i < EE; i += gridDim.x*blockDim.x) {
        int t = et[i];
        unsigned am = __activemask();
        unsigned m = __match_any_sync(am, t);
        int leader = __ffs(m) - 1;
        int base = 0;
        if (lane == leader) base = atomicAdd(&g_cursor[t], __popc(m));
        base = __shfl_sync(m, base, leader);
        int pos = base + __popc(m & ((1u << lane) - 1u));
        g_sorted[pos] = i;
    }
}

// transpose GRU weights to k-major AND round to tf32 (used only as MMA B operand)
__global__ void transpose_w_kernel(const float* __restrict__ wih, const float* __restrict__ whh) {
    for (int i = blockIdx.x*blockDim.x + threadIdx.x; i < 3*HH*HH; i += gridDim.x*blockDim.x) {
        int j = i >> 7;
        int k = i & 127;
        g_wT[k*384 + j] = tf32r(wih[i]);
        g_wT[HH*3*HH + k*384 + j] = tf32r(whh[i]);
    }
}

__global__ void round_weights_kernel(const float* __restrict__ W1, const float* __restrict__ W2) {
    for (int i = blockIdx.x*blockDim.x + threadIdx.x; i < TT*144*HH; i += gridDim.x*blockDim.x)
        g_w1r[i] = tf32r(W1[i]);
    for (int i = blockIdx.x*blockDim.x + threadIdx.x; i < TT*HH*HH; i += gridDim.x*blockDim.x)
        g_w2r[i] = tf32r(W2[i]);
}

// ---------------- edge MLP via mma.sync tf32 (unchanged from R4) ----------------
#define XS_STRIDE 148
#define WS_STRIDE 136
#define HS_STRIDE 132
#define EDGE_DYN_FLOATS (128*XS_STRIDE + 144*WS_STRIDE)
#define EDGE_DYN_BYTES  (EDGE_DYN_FLOATS*4)

__global__ void __launch_bounds__(256, 1) edge_mma_kernel(
    const float* __restrict__ hx, const int* __restrict__ ei,
    const int* __restrict__ et, const float* __restrict__ ea,
    const float* __restrict__ b1, const float* __restrict__ b2)
{
    extern __shared__ float sm[];
    float* Xs = sm;
    float* Ws = sm + 128*XS_STRIDE;
    __shared__ int s_e[128], s_src[128], s_dst[128];
    __shared__ float s_b1[128], s_b2[128];
    __shared__ int s_type;

    const int base = blockIdx.x * 128;
    if (base >= g_padTotal) return;
    const int tid = threadIdx.x, wid = tid >> 5, lane = tid & 31;

    if (tid < 128) {
        int e = g_sorted[base + tid];
        s_e[tid]   = e;
        s_src[tid] = (e >= 0) ? ei[e] : 0;
        s_dst[tid] = (e >= 0) ? ei[EE + e] : -1;
    }
    if (tid == 0) s_type = et[g_sorted[base]];
    __syncthreads();
    const int ty = s_type;

    #pragma unroll
    for (int rr = 0; rr < 16; ++rr) {
        int m = wid*16 + rr;
        const float4* hrow = (const float4*)(hx + (size_t)s_src[m]*HH);
        float4 v = hrow[lane];
        v.x = tf32r(v.x); v.y = tf32r(v.y); v.z = tf32r(v.z); v.w = tf32r(v.w);
        *(float4*)&Xs[m*XS_STRIDE + lane*4] = v;
        if (lane < 4) {
            int e = s_e[m];
            float4 av = make_float4(0.f,0.f,0.f,0.f);
            if (e >= 0) {
                av = ((const float4*)(ea + (size_t)e*AA))[lane];
                av.x = tf32r(av.x); av.y = tf32r(av.y); av.z = tf32r(av.z); av.w = tf32r(av.w);
            }
            *(float4*)&Xs[m*XS_STRIDE + HH + lane*4] = av;
        }
    }
    {
        const float4* src = (const float4*)(g_w1r + (size_t)ty*144*HH);
        for (int i = tid; i < 144*32; i += 256) {
            int r = i >> 5, c = i & 31;
            *(float4*)&Ws[r*WS_STRIDE + c*4] = src[i];
        }
    }
    if (tid < 128) { s_b1[tid] = b1[ty*HH + tid]; s_b2[tid] = b2[ty*HH + tid]; }
    __syncthreads();

    const int m0 = (wid & 1)*64, n0 = (wid >> 1)*32;
    const int gid = lane >> 2, tg = lane & 3;

    float acc[4][4][4];
    #pragma unroll
    for (int mi = 0; mi < 4; ++mi)
        #pragma unroll
        for (int ni = 0; ni < 4; ++ni)
            #pragma unroll
            for (int r = 0; r < 4; ++r) acc[mi][ni][r] = 0.f;

    #pragma unroll 2
    for (int ks = 0; ks < 18; ++ks) {
        const int k0 = ks*8;
        float a[4][4], b[4][2];
        #pragma unroll
        for (int mi = 0; mi < 4; ++mi) {
            const float* p = &Xs[(m0 + mi*16 + gid)*XS_STRIDE + k0 + tg];
            a[mi][0] = p[0];
            a[mi][1] = p[8*XS_STRIDE];
            a[mi][2] = p[4];
            a[mi][3] = p[8*XS_STRIDE + 4];
        }
        #pragma unroll
        for (int ni = 0; ni < 4; ++ni) {
            const float* p = &Ws[(k0 + tg)*WS_STRIDE + n0 + ni*8 + gid];
            b[ni][0] = p[0];
            b[ni][1] = p[4*WS_STRIDE];
        }
        #pragma unroll
        for (int mi = 0; mi < 4; ++mi)
            #pragma unroll
            for (int ni = 0; ni < 4; ++ni)
                MMA_TF32(acc[mi][ni], a[mi], b[ni]);
    }

    __syncthreads();

    float* Hs = Xs;
    #pragma unroll
    for (int mi = 0; mi < 4; ++mi) {
        int r1 = m0 + mi*16 + gid;
        int r2 = r1 + 8;
        #pragma unroll
        for (int ni = 0; ni < 4; ++ni) {
            int cc = n0 + ni*8 + tg*2;
            float2 v1, v2;
            v1.x = tf32r(fmaxf(acc[mi][ni][0] + s_b1[cc],     0.f));
            v1.y = tf32r(fmaxf(acc[mi][ni][1] + s_b1[cc + 1], 0.f));
            v2.x = tf32r(fmaxf(acc[mi][ni][2] + s_b1[cc],     0.f));
            v2.y = tf32r(fmaxf(acc[mi][ni][3] + s_b1[cc + 1], 0.f));
            *(float2*)&Hs[r1*HS_STRIDE + cc] = v1;
            *(float2*)&Hs[r2*HS_STRIDE + cc] = v2;
        }
    }
    {
        const float4* src = (const float4*)(g_w2r + (size_t)ty*HH*HH);
        for (int i = tid; i < 128*32; i += 256) {
            int r = i >> 5, c = i & 31;
            *(float4*)&Ws[r*WS_STRIDE + c*4] = src[i];
        }
    }
    __syncthreads();

    #pragma unroll
    for (int mi = 0; mi < 4; ++mi)
        #pragma unroll
        for (int ni = 0; ni < 4; ++ni)
            #pragma unroll
            for (int r = 0; r < 4; ++r) acc[mi][ni][r] = 0.f;

    #pragma unroll 2
    for (int ks = 0; ks < 16; ++ks) {
        const int k0 = ks*8;
        float a[4][4], b[4][2];
        #pragma unroll
        for (int mi = 0; mi < 4; ++mi) {
            const float* p = &Hs[(m0 + mi*16 + gid)*HS_STRIDE + k0 + tg];
            a[mi][0] = p[0];
            a[mi][1] = p[8*HS_STRIDE];
            a[mi][2] = p[4];
            a[mi][3] = p[8*HS_STRIDE + 4];
        }
        #pragma unroll
        for (int ni = 0; ni < 4; ++ni) {
            const float* p = &Ws[(k0 + tg)*WS_STRIDE + n0 + ni*8 + gid];
            b[ni][0] = p[0];
            b[ni][1] = p[4*WS_STRIDE];
        }
        #pragma unroll
        for (int mi = 0; mi < 4; ++mi)
            #pragma unroll
            for (int ni = 0; ni < 4; ++ni)
                MMA_TF32(acc[mi][ni], a[mi], b[ni]);
    }

    #pragma unroll
    for (int mi = 0; mi < 4; ++mi) {
        int r1 = m0 + mi*16 + gid;
        int r2 = r1 + 8;
        int d1 = s_dst[r1], d2 = s_dst[r2];
        #pragma unroll
        for (int ni = 0; ni < 4; ++ni) {
            int cc = n0 + ni*8 + tg*2;
            float v0 = acc[mi][ni][0] + s_b2[cc];
            float v1 = acc[mi][ni][1] + s_b2[cc + 1];
            float v2 = acc[mi][ni][2] + s_b2[cc];
            float v3 = acc[mi][ni][3] + s_b2[cc + 1];
            if (d1 >= 0)
                asm volatile("red.global.add.v2.f32 [%0], {%1, %2};"
                    :: "l"(g_msg + (size_t)d1*HH + cc), "f"(v0), "f"(v1) : "memory");
            if (d2 >= 0)
                asm volatile("red.global.add.v2.f32 [%0], {%1, %2};"
                    :: "l"(g_msg + (size_t)d2*HH + cc), "f"(v2), "f"(v3) : "memory");
        }
    }
}

// ---------------- GRU via mma.sync tf32 ----------------
// CTA: 256 threads / 8 warps, 128 nodes.
// SMEM: Ms[128x132] + Hs[128x132] (tf32-rounded A) + Bs[64x72] weight chunk.
// Per 64-col j-chunk: gates r -> n -> z; z pass fuses the output.
#define GMS 132
#define GBS 72
#define GRU_DYN_FLOATS (128*GMS*2 + 64*GBS)
#define GRU_DYN_BYTES  (GRU_DYN_FLOATS*4)

__device__ __forceinline__ float sigmoidf_(float x) { return 1.f / (1.f + __expf(-x)); }

// accumulate acc += A[128x128] @ W[:, jbase:jbase+64] (warp's 32-col slice)
__device__ __forceinline__ void gru_gemm_acc(
    float acc[2][4][4], const float* __restrict__ A,
    const float* __restrict__ wsrc, int jbase, float* Bs,
    int tid, int m0, int n0w, int gid, int tg)
{
    #pragma unroll
    for (int kc = 0; kc < 2; ++kc) {
        __syncthreads();
        for (int i = tid; i < 64*16; i += 256) {
            int kk = i >> 4, c = i & 15;
            float4 v = *(const float4*)&wsrc[(kc*64 + kk)*384 + jbase + c*4];
            *(float4*)&Bs[kk*GBS + c*4] = v;
        }
        __syncthreads();
        #pragma unroll
        for (int ks = 0; ks < 8; ++ks) {
            const int k0 = kc*64 + ks*8;
            const int kb = ks*8;
            float a[2][4], b[4][2];
            #pragma unroll
            for (int mi = 0; mi < 2; ++mi) {
                const float* p = &A[(m0 + mi*16 + gid)*GMS + k0 + tg];
                a[mi][0] = p[0];
                a[mi][1] = p[8*GMS];
                a[mi][2] = p[4];
                a[mi][3] = p[8*GMS + 4];
            }
            #pragma unroll
            for (int ni = 0; ni < 4; ++ni) {
                const float* q = &Bs[(kb + tg)*GBS + n0w + ni*8 + gid];
                b[ni][0] = q[0];
                b[ni][1] = q[4*GBS];
            }
            #pragma unroll
            for (int mi = 0; mi < 2; ++mi)
                #pragma unroll
                for (int ni = 0; ni < 4; ++ni)
                    MMA_TF32(acc[mi][ni], a[mi], b[ni]);
        }
    }
}

__global__ void __launch_bounds__(256, 1) gru_mma_kernel(
    const float* __restrict__ hx, const float* __restrict__ bih,
    const float* __restrict__ bhh, float* __restrict__ out)
{
    extern __shared__ float sm[];
    float* Ms = sm;               // 128 x 132
    float* Hs = Ms + 128*GMS;     // 128 x 132
    float* Bs = Hs + 128*GMS;     // 64 x 72

    const int tid = threadIdx.x, wid = tid >> 5, lane = tid & 31;
    const int gid = lane >> 2, tg = lane & 3;
    const int nbase = blockIdx.x * 128;
    const float* wih_t = g_wT;
    const float* whh_t = g_wT + HH*3*HH;

    // stage A (tf32-rounded msg & h)
    for (int i = tid; i < 128*32; i += 256) {
        int row = i >> 5, c = i & 31;
        int node = nbase + row;
        float4 mv = make_float4(0.f,0.f,0.f,0.f), hv = mv;
        if (node < NN) {
            mv = ((const float4*)(g_msg + (size_t)node*HH))[c];
            hv = ((const float4*)(hx + (size_t)node*HH))[c];
        }
        mv.x = tf32r(mv.x); mv.y = tf32r(mv.y); mv.z = tf32r(mv.z); mv.w = tf32r(mv.w);
        hv.x = tf32r(hv.x); hv.y = tf32r(hv.y); hv.z = tf32r(hv.z); hv.w = tf32r(hv.w);
        *(float4*)&Ms[row*GMS + c*4] = mv;
        *(float4*)&Hs[row*GMS + c*4] = hv;
    }

    const int m0 = (wid & 3)*32;       // node offset of warp tile (32 rows)
    const int n0w = (wid >> 2)*32;     // col offset within 64-col j-chunk

    #pragma unroll
    for (int jc = 0; jc < 2; ++jc) {
        const int jb = jc*64;          // col base within H

        // ---- gate r (rows 0:128 of gate dim) ----
        float racc[2][4][4];
        #pragma unroll
        for (int mi = 0; mi < 2; ++mi)
            #pragma unroll
            for (int ni = 0; ni < 4; ++ni)
                #pragma unroll
                for (int r = 0; r < 4; ++r) racc[mi][ni][r] = 0.f;
        gru_gemm_acc(racc, Ms, wih_t, 0 + jb, Bs, tid, m0, n0w, gid, tg);
        gru_gemm_acc(racc, Hs, whh_t, 0 + jb, Bs, tid, m0, n0w, gid, tg);
        #pragma unroll
        for (int mi = 0; mi < 2; ++mi)
            #pragma unroll
            for (int ni = 0; ni < 4; ++ni) {
                int c = jb + n0w + ni*8 + tg*2;
                float b0 = __ldg(bih + c)     + __ldg(bhh + c);
                float b1 = __ldg(bih + c + 1) + __ldg(bhh + c + 1);
                racc[mi][ni][0] = sigmoidf_(racc[mi][ni][0] + b0);
                racc[mi][ni][1] = sigmoidf_(racc[mi][ni][1] + b1);
                racc[mi][ni][2] = sigmoidf_(racc[mi][ni][2] + b0);
                racc[mi][ni][3] = sigmoidf_(racc[mi][ni][3] + b1);
            }

        // ---- gate n (rows 256:384): ng = tanh(i_n + bi + r*(h_n + bh)) ----
        float nacc[2][4][4];  // h_n accumulation first
        #pragma unroll
        for (int mi = 0; mi < 2; ++mi)
            #pragma unroll
            for (int ni = 0; ni < 4; ++ni)
                #pragma unroll
                for (int r = 0; r < 4; ++r) nacc[mi][ni][r] = 0.f;
        gru_gemm_acc(nacc, Hs, whh_t, 256 + jb, Bs, tid, m0, n0w, gid, tg);
        // t = r*(h_n + bh) stored back into racc (r dead after)
        #pragma unroll
        for (int mi = 0; mi < 2; ++mi)
            #pragma unroll
            for (int ni = 0; ni < 4; ++ni) {
                int c = jb + n0w + ni*8 + tg*2;
                float b0 = __ldg(bhh + 256 + c);
                float b1 = __ldg(bhh + 256 + c + 1);
                racc[mi][ni][0] = racc[mi][ni][0]*(nacc[mi][ni][0] + b0);
                racc[mi][ni][1] = racc[mi][ni][1]*(nacc[mi][ni][1] + b1);
                racc[mi][ni][2] = racc[mi][ni][2]*(nacc[mi][ni][2] + b0);
                racc[mi][ni][3] = racc[mi][ni][3]*(nacc[mi][ni][3] + b1);
                #pragma unroll
                for (int r = 0; r < 4; ++r) nacc[mi][ni][r] = 0.f;
            }
        gru_gemm_acc(nacc, Ms, wih_t, 256 + jb, Bs, tid, m0, n0w, gid, tg);
        // ng -> nacc
        #pragma unroll
        for (int mi = 0; mi < 2; ++mi)
            #pragma unroll
            for (int ni = 0; ni < 4; ++ni) {
                int c = jb + n0w + ni*8 + tg*2;
                float b0 = __ldg(bih + 256 + c);
                float b1 = __ldg(bih + 256 + c + 1);
                nacc[mi][ni][0] = tanhf(nacc[mi][ni][0] + b0 + racc[mi][ni][0]);
                nacc[mi][ni][1] = tanhf(nacc[mi][ni][1] + b1 + racc[mi][ni][1]);
                nacc[mi][ni][2] = tanhf(nacc[mi][ni][2] + b0 + racc[mi][ni][2]);
                nacc[mi][ni][3] = tanhf(nacc[mi][ni][3] + b1 + racc[mi][ni][3]);
            }

        // ---- gate z (rows 128:256) + output (racc reused as z acc) ----
        #pragma unroll
        for (int mi = 0; mi < 2; ++mi)
            #pragma unroll
            for (int ni = 0; ni < 4; ++ni)
                #pragma unroll
                for (int r = 0; r < 4; ++r) racc[mi][ni][r] = 0.f;
        gru_gemm_acc(racc, Ms, wih_t, 128 + jb, Bs, tid, m0, n0w, gid, tg);
        gru_gemm_acc(racc, Hs, whh_t, 128 + jb, Bs, tid, m0, n0w, gid, tg);
        #pragma unroll
        for (int mi = 0; mi < 2; ++mi) {
            int r1 = m0 + mi*16 + gid;
            int r2 = r1 + 8;
            int n1 = nbase + r1, n2 = nbase + r2;
            #pragma unroll
            for (int ni = 0; ni < 4; ++ni) {
                int c = jb + n0w + ni*8 + tg*2;
                float b0 = __ldg(bih + 128 + c)     + __ldg(bhh + 128 + c);
                float b1 = __ldg(bih + 128 + c + 1) + __ldg(bhh + 128 + c + 1);
                if (n1 < NN) {
                    float2 hv = *(const float2*)(hx + (size_t)n1*HH + c);
                    float z0 = sigmoidf_(racc[mi][ni][0] + b0);
                    float z1 = sigmoidf_(racc[mi][ni][1] + b1);
                    float2 o;
                    o.x = (1.f - z0)*nacc[mi][ni][0] + z0*hv.x;
                    o.y = (1.f - z1)*nacc[mi][ni][1] + z1*hv.y;
                    *(float2*)(out + (size_t)n1*HH + c) = o;
                }
                if (n2 < NN) {
                    float2 hv = *(const float2*)(hx + (size_t)n2*HH + c);
                    float z0 = sigmoidf_(racc[mi][ni][2] + b0);
                    float z1 = sigmoidf_(racc[mi][ni][3] + b1);
                    float2 o;
                    o.x = (1.f - z0)*nacc[mi][ni][2] + z0*hv.x;
                    o.y = (1.f - z1)*nacc[mi][ni][3] + z1*hv.y;
                    *(float2*)(out + (size_t)n2*HH + c) = o;
                }
            }
        }
    }
}

// ---------------- launcher ----------------
extern "C" void kernel_launch(void* const* d_in, const int* in_sizes, int n_in,
                              void* d_out, int out_size)
{
    const float* hx  = (const float*)d_in[0];
    const int*   ei  = (const int*)d_in[1];
    const int*   et  = (const int*)d_in[2];
    const float* ea  = (const float*)d_in[3];
    const float* W1  = (const float*)d_in[4];
    const float* b1  = (const float*)d_in[5];
    const float* W2  = (const float*)d_in[6];
    const float* b2  = (const float*)d_in[7];
    const float* wih = (const float*)d_in[8];
    const float* whh = (const float*)d_in[9];
    const float* bih = (const float*)d_in[10];
    const float* bhh = (const float*)d_in[11];
    float* out = (float*)d_out;

    cudaFuncSetAttribute(edge_mma_kernel, cudaFuncAttributeMaxDynamicSharedMemorySize, EDGE_DYN_BYTES);
    cudaFuncSetAttribute(gru_mma_kernel, cudaFuncAttributeMaxDynamicSharedMemorySize, GRU_DYN_BYTES);

    zero_counts_kernel<<<1, 32>>>();
    zero_msg_kernel<<<2048, 256>>>();
    fill_sorted_kernel<<<1024, 256>>>();
    hist_kernel<<<800, 256>>>(et);
    scan_kernel<<<1, 32>>>();
    scatter_kernel<<<800, 256>>>(et);
    transpose_w_kernel<<<192, 256>>>(wih, whh);
    round_weights_kernel<<<256, 256>>>(W1, W2);

    edge_mma_kernel<<<SORT_CAP/128, 256, EDGE_DYN_BYTES>>>(hx, ei, et, ea, b1, b2);
    gru_mma_kernel<<<(NN + 127)/128, 256, GRU_DYN_BYTES>>>(hx, bih, bhh, out);
}

// round 16
// speedup vs baseline: 1.0061x; 1.0061x over previous
#include <cuda_runtime.h>
#include <cstdint>

#define NN 50000
#define HH 128
#define EE 800000
#define AA 16
#define TT 4
#define SORT_CAP (EE + 128*TT)

// ---------------- device scratch ----------------
__device__ float g_msg[NN*HH];
__device__ int   g_sorted[SORT_CAP];
__device__ int   g_count[TT];
__device__ int   g_cursor[TT];
__device__ int   g_padTotal;
__device__ float g_wT[2*HH*3*HH];      // GRU weights transposed k-major, tf32-rounded
__device__ float g_w1r[TT*144*HH];     // tf32-rounded W1
__device__ float g_w2r[TT*HH*HH];      // tf32-rounded W2

// ---------------- helpers ----------------
__device__ __forceinline__ float tf32r(float x) {
    uint32_t u;
    asm("cvt.rna.tf32.f32 %0, %1;" : "=r"(u) : "f"(x));
    return __uint_as_float(u);
}

#define MMA_TF32(d, a, b) \
    asm volatile("mma.sync.aligned.m16n8k8.row.col.f32.tf32.tf32.f32 " \
        "{%0,%1,%2,%3}, {%4,%5,%6,%7}, {%8,%9}, {%0,%1,%2,%3};" \
        : "+f"((d)[0]), "+f"((d)[1]), "+f"((d)[2]), "+f"((d)[3]) \
        : "r"(__float_as_uint((a)[0])), "r"(__float_as_uint((a)[1])), \
          "r"(__float_as_uint((a)[2])), "r"(__float_as_uint((a)[3])), \
          "r"(__float_as_uint((b)[0])), "r"(__float_as_uint((b)[1])))

// ---------------- prep kernels ----------------
__global__ void zero_counts_kernel() { if (threadIdx.x < TT) g_count[threadIdx.x] = 0; }

__global__ void zero_msg_kernel() {
    const int n4 = NN*HH/4;
    for (int i = blockIdx.x*blockDim.x + threadIdx.x; i < n4; i += gridDim.x*blockDim.x)
        ((float4*)g_msg)[i] = make_float4(0.f,0.f,0.f,0.f);
}

__global__ void fill_sorted_kernel() {
    for (int i = blockIdx.x*blockDim.x + threadIdx.x; i < SORT_CAP; i += gridDim.x*blockDim.x)
        g_sorted[i] = -1;
}

__global__ void hist_kernel(const int* __restrict__ et) {
    const int lane = threadIdx.x & 31;
    for (int i = blockIdx.x*blockDim.x + threadIdx.x; i < EE; i += gridDim.x*blockDim.x) {
        int t = et[i];
        unsigned am = __activemask();
        unsigned m = __match_any_sync(am, t);
        int leader = __ffs(m) - 1;
        if (lane == leader) atomicAdd(&g_count[t], __popc(m));
    }
}

__global__ void scan_kernel() {
    if (threadIdx.x == 0 && blockIdx.x == 0) {
        int po = 0;
        for (int t = 0; t < TT; ++t) {
            g_cursor[t] = po;
            po += (g_count[t] + 127) & ~127;
        }
        g_padTotal = po;
    }
}

__global__ void scatter_kernel(const int* __restrict__ et) {
    const int lane = threadIdx.x & 31;
    for (int i = blockIdx.x*blockDim.x + threadIdx.x; i < EE; i += gridDim.x*blockDim.x) {
        int t = et[i];
        unsigned am = __activemask();
        unsigned m = __match_any_sync(am, t);
        int leader = __ffs(m) - 1;
        int base = 0;
        if (lane == leader) base = atomicAdd(&g_cursor[t], __popc(m));
        base = __shfl_sync(m, base, leader);
        int pos = base + __popc(m & ((1u << lane) - 1u));
        g_sorted[pos] = i;
    }
}

// transpose GRU weights to k-major AND round to tf32 (used only as MMA B operand)
__global__ void transpose_w_kernel(const float* __restrict__ wih, const float* __restrict__ whh) {
    for (int i = blockIdx.x*blockDim.x + threadIdx.x; i < 3*HH*HH; i += gridDim.x*blockDim.x) {
        int j = i >> 7;
        int k = i & 127;
        g_wT[k*384 + j] = tf32r(wih[i]);
        g_wT[HH*3*HH + k*384 + j] = tf32r(whh[i]);
    }
}

__global__ void round_weights_kernel(const float* __restrict__ W1, const float* __restrict__ W2) {
    for (int i = blockIdx.x*blockDim.x + threadIdx.x; i < TT*144*HH; i += gridDim.x*blockDim.x)
        g_w1r[i] = tf32r(W1[i]);
    for (int i = blockIdx.x*blockDim.x + threadIdx.x; i < TT*HH*HH; i += gridDim.x*blockDim.x)
        g_w2r[i] = tf32r(W2[i]);
}

// ---------------- edge MLP via mma.sync tf32 (unchanged from R4) ----------------
#define XS_STRIDE 148
#define WS_STRIDE 136
#define HS_STRIDE 132
#define EDGE_DYN_FLOATS (128*XS_STRIDE + 144*WS_STRIDE)
#define EDGE_DYN_BYTES  (EDGE_DYN_FLOATS*4)

__global__ void __launch_bounds__(256, 1) edge_mma_kernel(
    const float* __restrict__ hx, const int* __restrict__ ei,
    const int* __restrict__ et, const float* __restrict__ ea,
    const float* __restrict__ b1, const float* __restrict__ b2)
{
    extern __shared__ float sm[];
    float* Xs = sm;
    float* Ws = sm + 128*XS_STRIDE;
    __shared__ int s_e[128], s_src[128], s_dst[128];
    __shared__ float s_b1[128], s_b2[128];
    __shared__ int s_type;

    const int base = blockIdx.x * 128;
    if (base >= g_padTotal) return;
    const int tid = threadIdx.x, wid = tid >> 5, lane = tid & 31;

    if (tid < 128) {
        int e = g_sorted[base + tid];
        s_e[tid]   = e;
        s_src[tid] = (e >= 0) ? ei[e] : 0;
        s_dst[tid] = (e >= 0) ? ei[EE + e] : -1;
    }
    if (tid == 0) s_type = et[g_sorted[base]];
    __syncthreads();
    const int ty = s_type;

    #pragma unroll
    for (int rr = 0; rr < 16; ++rr) {
        int m = wid*16 + rr;
        const float4* hrow = (const float4*)(hx + (size_t)s_src[m]*HH);
        float4 v = hrow[lane];
        v.x = tf32r(v.x); v.y = tf32r(v.y); v.z = tf32r(v.z); v.w = tf32r(v.w);
        *(float4*)&Xs[m*XS_STRIDE + lane*4] = v;
        if (lane < 4) {
            int e = s_e[m];
            float4 av = make_float4(0.f,0.f,0.f,0.f);
            if (e >= 0) {
                av = ((const float4*)(ea + (size_t)e*AA))[lane];
                av.x = tf32r(av.x); av.y = tf32r(av.y); av.z = tf32r(av.z); av.w = tf32r(av.w);
            }
            *(float4*)&Xs[m*XS_STRIDE + HH + lane*4] = av;
        }
    }
    {
        const float4* src = (const float4*)(g_w1r + (size_t)ty*144*HH);
        for (int i = tid; i < 144*32; i += 256) {
            int r = i >> 5, c = i & 31;
            *(float4*)&Ws[r*WS_STRIDE + c*4] = src[i];
        }
    }
    if (tid < 128) { s_b1[tid] = b1[ty*HH + tid]; s_b2[tid] = b2[ty*HH + tid]; }
    __syncthreads();

    const int m0 = (wid & 1)*64, n0 = (wid >> 1)*32;
    const int gid = lane >> 2, tg = lane & 3;

    float acc[4][4][4];
    #pragma unroll
    for (int mi = 0; mi < 4; ++mi)
        #pragma unroll
        for (int ni = 0; ni < 4; ++ni)
            #pragma unroll
            for (int r = 0; r < 4; ++r) acc[mi][ni][r] = 0.f;

    #pragma unroll 2
    for (int ks = 0; ks < 18; ++ks) {
        const int k0 = ks*8;
        float a[4][4], b[4][2];
        #pragma unroll
        for (int mi = 0; mi < 4; ++mi) {
            const float* p = &Xs[(m0 + mi*16 + gid)*XS_STRIDE + k0 + tg];
            a[mi][0] = p[0];
            a[mi][1] = p[8*XS_STRIDE];
            a[mi][2] = p[4];
            a[mi][3] = p[8*XS_STRIDE + 4];
        }
        #pragma unroll
        for (int ni = 0; ni < 4; ++ni) {
            const float* p = &Ws[(k0 + tg)*WS_STRIDE + n0 + ni*8 + gid];
            b[ni][0] = p[0];
            b[ni][1] = p[4*WS_STRIDE];
        }
        #pragma unroll
        for (int mi = 0; mi < 4; ++mi)
            #pragma unroll
            for (int ni = 0; ni < 4; ++ni)
                MMA_TF32(acc[mi][ni], a[mi], b[ni]);
    }

    __syncthreads();

    float* Hs = Xs;
    #pragma unroll
    for (int mi = 0; mi < 4; ++mi) {
        int r1 = m0 + mi*16 + gid;
        int r2 = r1 + 8;
        #pragma unroll
        for (int ni = 0; ni < 4; ++ni) {
            int cc = n0 + ni*8 + tg*2;
            float2 v1, v2;
            v1.x = tf32r(fmaxf(acc[mi][ni][0] + s_b1[cc],     0.f));
            v1.y = tf32r(fmaxf(acc[mi][ni][1] + s_b1[cc + 1], 0.f));
            v2.x = tf32r(fmaxf(acc[mi][ni][2] + s_b1[cc],     0.f));
            v2.y = tf32r(fmaxf(acc[mi][ni][3] + s_b1[cc + 1], 0.f));
            *(float2*)&Hs[r1*HS_STRIDE + cc] = v1;
            *(float2*)&Hs[r2*HS_STRIDE + cc] = v2;
        }
    }
    {
        const float4* src = (const float4*)(g_w2r + (size_t)ty*HH*HH);
        for (int i = tid; i < 128*32; i += 256) {
            int r = i >> 5, c = i & 31;
            *(float4*)&Ws[r*WS_STRIDE + c*4] = src[i];
        }
    }
    __syncthreads();

    #pragma unroll
    for (int mi = 0; mi < 4; ++mi)
        #pragma unroll
        for (int ni = 0; ni < 4; ++ni)
            #pragma unroll
            for (int r = 0; r < 4; ++r) acc[mi][ni][r] = 0.f;

    #pragma unroll 2
    for (int ks = 0; ks < 16; ++ks) {
        const int k0 = ks*8;
        float a[4][4], b[4][2];
        #pragma unroll
        for (int mi = 0; mi < 4; ++mi) {
            const float* p = &Hs[(m0 + mi*16 + gid)*HS_STRIDE + k0 + tg];
            a[mi][0] = p[0];
            a[mi][1] = p[8*HS_STRIDE];
            a[mi][2] = p[4];
            a[mi][3] = p[8*HS_STRIDE + 4];
        }
        #pragma unroll
        for (int ni = 0; ni < 4; ++ni) {
            const float* p = &Ws[(k0 + tg)*WS_STRIDE + n0 + ni*8 + gid];
            b[ni][0] = p[0];
            b[ni][1] = p[4*WS_STRIDE];
        }
        #pragma unroll
        for (int mi = 0; mi < 4; ++mi)
            #pragma unroll
            for (int ni = 0; ni < 4; ++ni)
                MMA_TF32(acc[mi][ni], a[mi], b[ni]);
    }

    #pragma unroll
    for (int mi = 0; mi < 4; ++mi) {
        int r1 = m0 + mi*16 + gid;
        int r2 = r1 + 8;
        int d1 = s_dst[r1], d2 = s_dst[r2];
        #pragma unroll
        for (int ni = 0; ni < 4; ++ni) {
            int cc = n0 + ni*8 + tg*2;
            float v0 = acc[mi][ni][0] + s_b2[cc];
            float v1 = acc[mi][ni][1] + s_b2[cc + 1];
            float v2 = acc[mi][ni][2] + s_b2[cc];
            float v3 = acc[mi][ni][3] + s_b2[cc + 1];
            if (d1 >= 0)
                asm volatile("red.global.add.v2.f32 [%0], {%1, %2};"
                    :: "l"(g_msg + (size_t)d1*HH + cc), "f"(v0), "f"(v1) : "memory");
            if (d2 >= 0)
                asm volatile("red.global.add.v2.f32 [%0], {%1, %2};"
                    :: "l"(g_msg + (size_t)d2*HH + cc), "f"(v2), "f"(v3) : "memory");
        }
    }
}

// ---------------- GRU via mma.sync tf32 ----------------
// CTA: 256 threads / 8 warps, 128 nodes.
// SMEM: Ms[128x132] + Hs[128x132] (tf32-rounded A) + Bs[64x72] weight chunk.
// Per 64-col j-chunk: gates r -> n -> z; z pass fuses the output.
#define GMS 132
#define GBS 72
#define GRU_DYN_FLOATS (128*GMS*2 + 64*GBS)
#define GRU_DYN_BYTES  (GRU_DYN_FLOATS*4)

__device__ __forceinline__ float sigmoidf_(float x) { return 1.f / (1.f + __expf(-x)); }

// accumulate acc += A[128x128] @ W[:, jbase:jbase+64] (warp's 32-col slice)
__device__ __forceinline__ void gru_gemm_acc(
    float acc[2][4][4], const float* __restrict__ A,
    const float* __restrict__ wsrc, int jbase, float* Bs,
    int tid, int m0, int n0w, int gid, int tg)
{
    #pragma unroll
    for (int kc = 0; kc < 2; ++kc) {
        __syncthreads();
        for (int i = tid; i < 64*16; i += 256) {
            int kk = i >> 4, c = i & 15;
            float4 v = *(const float4*)&wsrc[(kc*64 + kk)*384 + jbase + c*4];
            *(float4*)&Bs[kk*GBS + c*4] = v;
        }
        __syncthreads();
        #pragma unroll
        for (int ks = 0; ks < 8; ++ks) {
            const int k0 = kc*64 + ks*8;
            const int kb = ks*8;
            float a[2][4], b[4][2];
            #pragma unroll
            for (int mi = 0; mi < 2; ++mi) {
                const float* p = &A[(m0 + mi*16 + gid)*GMS + k0 + tg];
                a[mi][0] = p[0];
                a[mi][1] = p[8*GMS];
                a[mi][2] = p[4];
                a[mi][3] = p[8*GMS + 4];
            }
            #pragma unroll
            for (int ni = 0; ni < 4; ++ni) {
                const float* q = &Bs[(kb + tg)*GBS + n0w + ni*8 + gid];
                b[ni][0] = q[0];
                b[ni][1] = q[4*GBS];
            }
            #pragma unroll
            for (int mi = 0; mi < 2; ++mi)
                #pragma unroll
                for (int ni = 0; ni < 4; ++ni)
                    MMA_TF32(acc[mi][ni], a[mi], b[ni]);
        }
    }
}

__global__ void __launch_bounds__(256, 1) gru_mma_kernel(
    const float* __restrict__ hx, const float* __restrict__ bih,
    const float* __restrict__ bhh, float* __restrict__ out)
{
    extern __shared__ float sm[];
    float* Ms = sm;               // 128 x 132
    float* Hs = Ms + 128*GMS;     // 128 x 132
    float* Bs = Hs + 128*GMS;     // 64 x 72

    const int tid = threadIdx.x, wid = tid >> 5, lane = tid & 31;
    const int gid = lane >> 2, tg = lane & 3;
    const int nbase = blockIdx.x * 128;
    const float* wih_t = g_wT;
    const float* whh_t = g_wT + HH*3*HH;

    // stage A (tf32-rounded msg & h)
    for (int i = tid; i < 128*32; i += 256) {
        int row = i >> 5, c = i & 31;
        int node = nbase + row;
        float4 mv = make_float4(0.f,0.f,0.f,0.f), hv = mv;
        if (node < NN) {
            mv = ((const float4*)(g_msg + (size_t)node*HH))[c];
            hv = ((const float4*)(hx + (size_t)node*HH))[c];
        }
        mv.x = tf32r(mv.x); mv.y = tf32r(mv.y); mv.z = tf32r(mv.z); mv.w = tf32r(mv.w);
        hv.x = tf32r(hv.x); hv.y = tf32r(hv.y); hv.z = tf32r(hv.z); hv.w = tf32r(hv.w);
        *(float4*)&Ms[row*GMS + c*4] = mv;
        *(float4*)&Hs[row*GMS + c*4] = hv;
    }

    const int m0 = (wid & 3)*32;       // node offset of warp tile (32 rows)
    const int n0w = (wid >> 2)*32;     // col offset within 64-col j-chunk

    #pragma unroll
    for (int jc = 0; jc < 2; ++jc) {
        const int jb = jc*64;          // col base within H

        // ---- gate r (rows 0:128 of gate dim) ----
        float racc[2][4][4];
        #pragma unroll
        for (int mi = 0; mi < 2; ++mi)
            #pragma unroll
            for (int ni = 0; ni < 4; ++ni)
                #pragma unroll
                for (int r = 0; r < 4; ++r) racc[mi][ni][r] = 0.f;
        gru_gemm_acc(racc, Ms, wih_t, 0 + jb, Bs, tid, m0, n0w, gid, tg);
        gru_gemm_acc(racc, Hs, whh_t, 0 + jb, Bs, tid, m0, n0w, gid, tg);
        #pragma unroll
        for (int mi = 0; mi < 2; ++mi)
            #pragma unroll
            for (int ni = 0; ni < 4; ++ni) {
                int c = jb + n0w + ni*8 + tg*2;
                float b0 = __ldg(bih + c)     + __ldg(bhh + c);
                float b1 = __ldg(bih + c + 1) + __ldg(bhh + c + 1);
                racc[mi][ni][0] = sigmoidf_(racc[mi][ni][0] + b0);
                racc[mi][ni][1] = sigmoidf_(racc[mi][ni][1] + b1);
                racc[mi][ni][2] = sigmoidf_(racc[mi][ni][2] + b0);
                racc[mi][ni][3] = sigmoidf_(racc[mi][ni][3] + b1);
            }

        // ---- gate n (rows 256:384): ng = tanh(i_n + bi + r*(h_n + bh)) ----
        float nacc[2][4][4];  // h_n accumulation first
        #pragma unroll
        for (int mi = 0; mi < 2; ++mi)
            #pragma unroll
            for (int ni = 0; ni < 4; ++ni)
                #pragma unroll
                for (int r = 0; r < 4; ++r) nacc[mi][ni][r] = 0.f;
        gru_gemm_acc(nacc, Hs, whh_t, 256 + jb, Bs, tid, m0, n0w, gid, tg);
        // t = r*(h_n + bh) stored back into racc (r dead after)
        #pragma unroll
        for (int mi = 0; mi < 2; ++mi)
            #pragma unroll
            for (int ni = 0; ni < 4; ++ni) {
                int c = jb + n0w + ni*8 + tg*2;
                float b0 = __ldg(bhh + 256 + c);
                float b1 = __ldg(bhh + 256 + c + 1);
                racc[mi][ni][0] = racc[mi][ni][0]*(nacc[mi][ni][0] + b0);
                racc[mi][ni][1] = racc[mi][ni][1]*(nacc[mi][ni][1] + b1);
                racc[mi][ni][2] = racc[mi][ni][2]*(nacc[mi][ni][2] + b0);
                racc[mi][ni][3] = racc[mi][ni][3]*(nacc[mi][ni][3] + b1);
                #pragma unroll
                for (int r = 0; r < 4; ++r) nacc[mi][ni][r] = 0.f;
            }
        gru_gemm_acc(nacc, Ms, wih_t, 256 + jb, Bs, tid, m0, n0w, gid, tg);
        // ng -> nacc
        #pragma unroll
        for (int mi = 0; mi < 2; ++mi)
            #pragma unroll
            for (int ni = 0; ni < 4; ++ni) {
                int c = jb + n0w + ni*8 + tg*2;
                float b0 = __ldg(bih + 256 + c);
                float b1 = __ldg(bih + 256 + c + 1);
                nacc[mi][ni][0] = tanhf(nacc[mi][ni][0] + b0 + racc[mi][ni][0]);
                nacc[mi][ni][1] = tanhf(nacc[mi][ni][1] + b1 + racc[mi][ni][1]);
                nacc[mi][ni][2] = tanhf(nacc[mi][ni][2] + b0 + racc[mi][ni][2]);
                nacc[mi][ni][3] = tanhf(nacc[mi][ni][3] + b1 + racc[mi][ni][3]);
            }

        // ---- gate z (rows 128:256) + output (racc reused as z acc) ----
        #pragma unroll
        for (int mi = 0; mi < 2; ++mi)
            #pragma unroll
            for (int ni = 0; ni < 4; ++ni)
                #pragma unroll
                for (int r = 0; r < 4; ++r) racc[mi][ni][r] = 0.f;
        gru_gemm_acc(racc, Ms, wih_t, 128 + jb, Bs, tid, m0, n0w, gid, tg);
        gru_gemm_acc(racc, Hs, whh_t, 128 + jb, Bs, tid, m0, n0w, gid, tg);
        #pragma unroll
        for (int mi = 0; mi < 2; ++mi) {
            int r1 = m0 + mi*16 + gid;
            int r2 = r1 + 8;
            int n1 = nbase + r1, n2 = nbase + r2;
            #pragma unroll
            for (int ni = 0; ni < 4; ++ni) {
                int c = jb + n0w + ni*8 + tg*2;
                float b0 = __ldg(bih + 128 + c)     + __ldg(bhh + 128 + c);
                float b1 = __ldg(bih + 128 + c + 1) + __ldg(bhh + 128 + c + 1);
                if (n1 < NN) {
                    float2 hv = *(const float2*)(hx + (size_t)n1*HH + c);
                    float z0 = sigmoidf_(racc[mi][ni][0] + b0);
                    float z1 = sigmoidf_(racc[mi][ni][1] + b1);
                    float2 o;
                    o.x = (1.f - z0)*nacc[mi][ni][0] + z0*hv.x;
                    o.y = (1.f - z1)*nacc[mi][ni][1] + z1*hv.y;
                    *(float2*)(out + (size_t)n1*HH + c) = o;
                }
                if (n2 < NN) {
                    float2 hv = *(const float2*)(hx + (size_t)n2*HH + c);
                    float z0 = sigmoidf_(racc[mi][ni][2] + b0);
                    float z1 = sigmoidf_(racc[mi][ni][3] + b1);
                    float2 o;
                    o.x = (1.f - z0)*nacc[mi][ni][2] + z0*hv.x;
                    o.y = (1.f - z1)*nacc[mi][ni][3] + z1*hv.y;
                    *(float2*)(out + (size_t)n2*HH + c) = o;
                }
            }
        }
    }
}

// ---------------- launcher ----------------
extern "C" void kernel_launch(void* const* d_in, const int* in_sizes, int n_in,
                              void* d_out, int out_size)
{
    const float* hx  = (const float*)d_in[0];
    const int*   ei  = (const int*)d_in[1];
    const int*   et  = (const int*)d_in[2];
    const float* ea  = (const float*)d_in[3];
    const float* W1  = (const float*)d_in[4];
    const float* b1  = (const float*)d_in[5];
    const float* W2  = (const float*)d_in[6];
    const float* b2  = (const float*)d_in[7];
    const float* wih = (const float*)d_in[8];
    const float* whh = (const float*)d_in[9];
    const float* bih = (const float*)d_in[10];
    const float* bhh = (const float*)d_in[11];
    float* out = (float*)d_out;

    cudaFuncSetAttribute(edge_mma_kernel, cudaFuncAttributeMaxDynamicSharedMemorySize, EDGE_DYN_BYTES);
    cudaFuncSetAttribute(gru_mma_kernel, cudaFuncAttributeMaxDynamicSharedMemorySize, GRU_DYN_BYTES);

    zero_counts_kernel<<<1, 32>>>();
    zero_msg_kernel<<<2048, 256>>>();
    fill_sorted_kernel<<<1024, 256>>>();
    hist_kernel<<<800, 256>>>(et);
    scan_kernel<<<1, 32>>>();
    scatter_kernel<<<800, 256>>>(et);
    transpose_w_kernel<<<192, 256>>>(wih, whh);
    round_weights_kernel<<<256, 256>>>(W1, W2);

    edge_mma_kernel<<<SORT_CAP/128, 256, EDGE_DYN_BYTES>>>(hx, ei, et, ea, b1, b2);
    gru_mma_kernel<<<(NN + 127)/128, 256, GRU_DYN_BYTES>>>(hx, bih, bhh, out);
}

// round 17
// speedup vs baseline: 1.0085x; 1.0024x over previous
#include <cuda_runtime.h>
#include <cstdint>

#define NN 50000
#define HH 128
#define EE 800000
#define AA 16
#define TT 4
#define SORT_CAP (EE + 128*TT)

// ---------------- device scratch ----------------
__device__ float g_msg[NN*HH];
__device__ int   g_sorted[SORT_CAP];
__device__ int   g_count[TT];
__device__ int   g_cursor[TT];
__device__ int   g_padTotal;
__device__ float g_wT[2*HH*3*HH];      // GRU weights transposed k-major, tf32-rounded
__device__ float g_w1r[TT*144*HH];     // tf32-rounded W1
__device__ float g_w2r[TT*HH*HH];      // tf32-rounded W2

// ---------------- helpers ----------------
__device__ __forceinline__ float tf32r(float x) {
    uint32_t u;
    asm("cvt.rna.tf32.f32 %0, %1;" : "=r"(u) : "f"(x));
    return __uint_as_float(u);
}

#define MMA_TF32(d, a, b) \
    asm volatile("mma.sync.aligned.m16n8k8.row.col.f32.tf32.tf32.f32 " \
        "{%0,%1,%2,%3}, {%4,%5,%6,%7}, {%8,%9}, {%0,%1,%2,%3};" \
        : "+f"((d)[0]), "+f"((d)[1]), "+f"((d)[2]), "+f"((d)[3]) \
        : "r"(__float_as_uint((a)[0])), "r"(__float_as_uint((a)[1])), \
          "r"(__float_as_uint((a)[2])), "r"(__float_as_uint((a)[3])), \
          "r"(__float_as_uint((b)[0])), "r"(__float_as_uint((b)[1])))

// ---------------- prep kernels ----------------
__global__ void zero_counts_kernel() { if (threadIdx.x < TT) g_count[threadIdx.x] = 0; }

__global__ void zero_msg_kernel() {
    const int n4 = NN*HH/4;
    for (int i = blockIdx.x*blockDim.x + threadIdx.x; i < n4; i += gridDim.x*blockDim.x)
        ((float4*)g_msg)[i] = make_float4(0.f,0.f,0.f,0.f);
}

__global__ void fill_sorted_kernel() {
    for (int i = blockIdx.x*blockDim.x + threadIdx.x; i < SORT_CAP; i += gridDim.x*blockDim.x)
        g_sorted[i] = -1;
}

__global__ void hist_kernel(const int* __restrict__ et) {
    const int lane = threadIdx.x & 31;
    for (int i = blockIdx.x*blockDim.x + threadIdx.x; i < EE; i += gridDim.x*blockDim.x) {
        int t = et[i];
        unsigned am = __activemask();
        unsigned m = __match_any_sync(am, t);
        int leader = __ffs(m) - 1;
        if (lane == leader) atomicAdd(&g_count[t], __popc(m));
    }
}

__global__ void scan_kernel() {
    if (threadIdx.x == 0 && blockIdx.x == 0) {
        int po = 0;
        for (int t = 0; t < TT; ++t) {
            g_cursor[t] = po;
            po += (g_count[t] + 127) & ~127;
        }
        g_padTotal = po;
    }
}

__global__ void scatter_kernel(const int* __restrict__ et) {
    const int lane = threadIdx.x & 31;
    for (int i = blockIdx.x*blockDim.x + threadIdx.x; i < EE; i += gridDim.x*blockDim.x) {
        int t = et[i];
        unsigned am = __activemask();
        unsigned m = __match_any_sync(am, t);
        int leader = __ffs(m) - 1;
        int base = 0;
        if (lane == leader) base = atomicAdd(&g_cursor[t], __popc(m));
        base = __shfl_sync(m, base, leader);
        int pos = base + __popc(m & ((1u << lane) - 1u));
        g_sorted[pos] = i;
    }
}

// transpose GRU weights to k-major AND round to tf32 (used only as MMA B operand)
__global__ void transpose_w_kernel(const float* __restrict__ wih, const float* __restrict__ whh) {
    for (int i = blockIdx.x*blockDim.x + threadIdx.x; i < 3*HH*HH; i += gridDim.x*blockDim.x) {
        int j = i >> 7;
        int k = i & 127;
        g_wT[k*384 + j] = tf32r(wih[i]);
        g_wT[HH*3*HH + k*384 + j] = tf32r(whh[i]);
    }
}

__global__ void round_weights_kernel(const float* __restrict__ W1, const float* __restrict__ W2) {
    for (int i = blockIdx.x*blockDim.x + threadIdx.x; i < TT*144*HH; i += gridDim.x*blockDim.x)
        g_w1r[i] = tf32r(W1[i]);
    for (int i = blockIdx.x*blockDim.x + threadIdx.x; i < TT*HH*HH; i += gridDim.x*blockDim.x)
        g_w2r[i] = tf32r(W2[i]);
}

// ---------------- edge MLP via mma.sync tf32 (unchanged from R4) ----------------
#define XS_STRIDE 148
#define WS_STRIDE 136
#define HS_STRIDE 132
#define EDGE_DYN_FLOATS (128*XS_STRIDE + 144*WS_STRIDE)
#define EDGE_DYN_BYTES  (EDGE_DYN_FLOATS*4)

__global__ void __launch_bounds__(256, 1) edge_mma_kernel(
    const float* __restrict__ hx, const int* __restrict__ ei,
    const int* __restrict__ et, const float* __restrict__ ea,
    const float* __restrict__ b1, const float* __restrict__ b2)
{
    extern __shared__ float sm[];
    float* Xs = sm;
    float* Ws = sm + 128*XS_STRIDE;
    __shared__ int s_e[128], s_src[128], s_dst[128];
    __shared__ float s_b1[128], s_b2[128];
    __shared__ int s_type;

    const int base = blockIdx.x * 128;
    if (base >= g_padTotal) return;
    const int tid = threadIdx.x, wid = tid >> 5, lane = tid & 31;

    if (tid < 128) {
        int e = g_sorted[base + tid];
        s_e[tid]   = e;
        s_src[tid] = (e >= 0) ? ei[e] : 0;
        s_dst[tid] = (e >= 0) ? ei[EE + e] : -1;
    }
    if (tid == 0) s_type = et[g_sorted[base]];
    __syncthreads();
    const int ty = s_type;

    #pragma unroll
    for (int rr = 0; rr < 16; ++rr) {
        int m = wid*16 + rr;
        const float4* hrow = (const float4*)(hx + (size_t)s_src[m]*HH);
        float4 v = hrow[lane];
        v.x = tf32r(v.x); v.y = tf32r(v.y); v.z = tf32r(v.z); v.w = tf32r(v.w);
        *(float4*)&Xs[m*XS_STRIDE + lane*4] = v;
        if (lane < 4) {
            int e = s_e[m];
            float4 av = make_float4(0.f,0.f,0.f,0.f);
            if (e >= 0) {
                av = ((const float4*)(ea + (size_t)e*AA))[lane];
                av.x = tf32r(av.x); av.y = tf32r(av.y); av.z = tf32r(av.z); av.w = tf32r(av.w);
            }
            *(float4*)&Xs[m*XS_STRIDE + HH + lane*4] = av;
        }
    }
    {
        const float4* src = (const float4*)(g_w1r + (size_t)ty*144*HH);
        for (int i = tid; i < 144*32; i += 256) {
            int r = i >> 5, c = i & 31;
            *(float4*)&Ws[r*WS_STRIDE + c*4] = src[i];
        }
    }
    if (tid < 128) { s_b1[tid] = b1[ty*HH + tid]; s_b2[tid] = b2[ty*HH + tid]; }
    __syncthreads();

    const int m0 = (wid & 1)*64, n0 = (wid >> 1)*32;
    const int gid = lane >> 2, tg = lane & 3;

    float acc[4][4][4];
    #pragma unroll
    for (int mi = 0; mi < 4; ++mi)
        #pragma unroll
        for (int ni = 0; ni < 4; ++ni)
            #pragma unroll
            for (int r = 0; r < 4; ++r) acc[mi][ni][r] = 0.f;

    #pragma unroll 2
    for (int ks = 0; ks < 18; ++ks) {
        const int k0 = ks*8;
        float a[4][4], b[4][2];
        #pragma unroll
        for (int mi = 0; mi < 4; ++mi) {
            const float* p = &Xs[(m0 + mi*16 + gid)*XS_STRIDE + k0 + tg];
            a[mi][0] = p[0];
            a[mi][1] = p[8*XS_STRIDE];
            a[mi][2] = p[4];
            a[mi][3] = p[8*XS_STRIDE + 4];
        }
        #pragma unroll
        for (int ni = 0; ni < 4; ++ni) {
            const float* p = &Ws[(k0 + tg)*WS_STRIDE + n0 + ni*8 + gid];
            b[ni][0] = p[0];
            b[ni][1] = p[4*WS_STRIDE];
        }
        #pragma unroll
        for (int mi = 0; mi < 4; ++mi)
            #pragma unroll
            for (int ni = 0; ni < 4; ++ni)
                MMA_TF32(acc[mi][ni], a[mi], b[ni]);
    }

    __syncthreads();

    float* Hs = Xs;
    #pragma unroll
    for (int mi = 0; mi < 4; ++mi) {
        int r1 = m0 + mi*16 + gid;
        int r2 = r1 + 8;
        #pragma unroll
        for (int ni = 0; ni < 4; ++ni) {
            int cc = n0 + ni*8 + tg*2;
            float2 v1, v2;
            v1.x = tf32r(fmaxf(acc[mi][ni][0] + s_b1[cc],     0.f));
            v1.y = tf32r(fmaxf(acc[mi][ni][1] + s_b1[cc + 1], 0.f));
            v2.x = tf32r(fmaxf(acc[mi][ni][2] + s_b1[cc],     0.f));
            v2.y = tf32r(fmaxf(acc[mi][ni][3] + s_b1[cc + 1], 0.f));
            *(float2*)&Hs[r1*HS_STRIDE + cc] = v1;
            *(float2*)&Hs[r2*HS_STRIDE + cc] = v2;
        }
    }
    {
        const float4* src = (const float4*)(g_w2r + (size_t)ty*HH*HH);
        for (int i = tid; i < 128*32; i += 256) {
            int r = i >> 5, c = i & 31;
            *(float4*)&Ws[r*WS_STRIDE + c*4] = src[i];
        }
    }
    __syncthreads();

    #pragma unroll
    for (int mi = 0; mi < 4; ++mi)
        #pragma unroll
        for (int ni = 0; ni < 4; ++ni)
            #pragma unroll
            for (int r = 0; r < 4; ++r) acc[mi][ni][r] = 0.f;

    #pragma unroll 2
    for (int ks = 0; ks < 16; ++ks) {
        const int k0 = ks*8;
        float a[4][4], b[4][2];
        #pragma unroll
        for (int mi = 0; mi < 4; ++mi) {
            const float* p = &Hs[(m0 + mi*16 + gid)*HS_STRIDE + k0 + tg];
            a[mi][0] = p[0];
            a[mi][1] = p[8*HS_STRIDE];
            a[mi][2] = p[4];
            a[mi][3] = p[8*HS_STRIDE + 4];
        }
        #pragma unroll
        for (int ni = 0; ni < 4; ++ni) {
            const float* p = &Ws[(k0 + tg)*WS_STRIDE + n0 + ni*8 + gid];
            b[ni][0] = p[0];
            b[ni][1] = p[4*WS_STRIDE];
        }
        #pragma unroll
        for (int mi = 0; mi < 4; ++mi)
            #pragma unroll
            for (int ni = 0; ni < 4; ++ni)
                MMA_TF32(acc[mi][ni], a[mi], b[ni]);
    }

    #pragma unroll
    for (int mi = 0; mi < 4; ++mi) {
        int r1 = m0 + mi*16 + gid;
        int r2 = r1 + 8;
        int d1 = s_dst[r1], d2 = s_dst[r2];
        #pragma unroll
        for (int ni = 0; ni < 4; ++ni) {
            int cc = n0 + ni*8 + tg*2;
            float v0 = acc[mi][ni][0] + s_b2[cc];
            float v1 = acc[mi][ni][1] + s_b2[cc + 1];
            float v2 = acc[mi][ni][2] + s_b2[cc];
            float v3 = acc[mi][ni][3] + s_b2[cc + 1];
            if (d1 >= 0)
                asm volatile("red.global.add.v2.f32 [%0], {%1, %2};"
                    :: "l"(g_msg + (size_t)d1*HH + cc), "f"(v0), "f"(v1) : "memory");
            if (d2 >= 0)
                asm volatile("red.global.add.v2.f32 [%0], {%1, %2};"
                    :: "l"(g_msg + (size_t)d2*HH + cc), "f"(v2), "f"(v3) : "memory");
        }
    }
}

// ---------------- GRU via mma.sync tf32 ----------------
// CTA: 256 threads / 8 warps, 128 nodes.
// SMEM: Ms[128x132] + Hs[128x132] (tf32-rounded A) + Bs[64x72] weight chunk.
// Per 64-col j-chunk: gates r -> n -> z; z pass fuses the output.
#define GMS 132
#define GBS 72
#define GRU_DYN_FLOATS (128*GMS*2 + 64*GBS)
#define GRU_DYN_BYTES  (GRU_DYN_FLOATS*4)

__device__ __forceinline__ float sigmoidf_(float x) { return 1.f / (1.f + __expf(-x)); }

// accumulate acc += A[128x128] @ W[:, jbase:jbase+64] (warp's 32-col slice)
__device__ __forceinline__ void gru_gemm_acc(
    float acc[2][4][4], const float* __restrict__ A,
    const float* __restrict__ wsrc, int jbase, float* Bs,
    int tid, int m0, int n0w, int gid, int tg)
{
    #pragma unroll
    for (int kc = 0; kc < 2; ++kc) {
        __syncthreads();
        for (int i = tid; i < 64*16; i += 256) {
            int kk = i >> 4, c = i & 15;
            float4 v = *(const float4*)&wsrc[(kc*64 + kk)*384 + jbase + c*4];
            *(float4*)&Bs[kk*GBS + c*4] = v;
        }
        __syncthreads();
        #pragma unroll
        for (int ks = 0; ks < 8; ++ks) {
            const int k0 = kc*64 + ks*8;
            const int kb = ks*8;
            float a[2][4], b[4][2];
            #pragma unroll
            for (int mi = 0; mi < 2; ++mi) {
                const float* p = &A[(m0 + mi*16 + gid)*GMS + k0 + tg];
                a[mi][0] = p[0];
                a[mi][1] = p[8*GMS];
                a[mi][2] = p[4];
                a[mi][3] = p[8*GMS + 4];
            }
            #pragma unroll
            for (int ni = 0; ni < 4; ++ni) {
                const float* q = &Bs[(kb + tg)*GBS + n0w + ni*8 + gid];
                b[ni][0] = q[0];
                b[ni][1] = q[4*GBS];
            }
            #pragma unroll
            for (int mi = 0; mi < 2; ++mi)
                #pragma unroll
                for (int ni = 0; ni < 4; ++ni)
                    MMA_TF32(acc[mi][ni], a[mi], b[ni]);
        }
    }
}

__global__ void __launch_bounds__(256, 1) gru_mma_kernel(
    const float* __restrict__ hx, const float* __restrict__ bih,
    const float* __restrict__ bhh, float* __restrict__ out)
{
    extern __shared__ float sm[];
    float* Ms = sm;               // 128 x 132
    float* Hs = Ms + 128*GMS;     // 128 x 132
    float* Bs = Hs + 128*GMS;     // 64 x 72

    const int tid = threadIdx.x, wid = tid >> 5, lane = tid & 31;
    const int gid = lane >> 2, tg = lane & 3;
    const int nbase = blockIdx.x * 128;
    const float* wih_t = g_wT;
    const float* whh_t = g_wT + HH*3*HH;

    // stage A (tf32-rounded msg & h)
    for (int i = tid; i < 128*32; i += 256) {
        int row = i >> 5, c = i & 31;
        int node = nbase + row;
        float4 mv = make_float4(0.f,0.f,0.f,0.f), hv = mv;
        if (node < NN) {
            mv = ((const float4*)(g_msg + (size_t)node*HH))[c];
            hv = ((const float4*)(hx + (size_t)node*HH))[c];
        }
        mv.x = tf32r(mv.x); mv.y = tf32r(mv.y); mv.z = tf32r(mv.z); mv.w = tf32r(mv.w);
        hv.x = tf32r(hv.x); hv.y = tf32r(hv.y); hv.z = tf32r(hv.z); hv.w = tf32r(hv.w);
        *(float4*)&Ms[row*GMS + c*4] = mv;
        *(float4*)&Hs[row*GMS + c*4] = hv;
    }

    const int m0 = (wid & 3)*32;       // node offset of warp tile (32 rows)
    const int n0w = (wid >> 2)*32;     // col offset within 64-col j-chunk

    #pragma unroll
    for (int jc = 0; jc < 2; ++jc) {
        const int jb = jc*64;          // col base within H

        // ---- gate r (rows 0:128 of gate dim) ----
        float racc[2][4][4];
        #pragma unroll
        for (int mi = 0; mi < 2; ++mi)
            #pragma unroll
            for (int ni = 0; ni < 4; ++ni)
                #pragma unroll
                for (int r = 0; r < 4; ++r) racc[mi][ni][r] = 0.f;
        gru_gemm_acc(racc, Ms, wih_t, 0 + jb, Bs, tid, m0, n0w, gid, tg);
        gru_gemm_acc(racc, Hs, whh_t, 0 + jb, Bs, tid, m0, n0w, gid, tg);
        #pragma unroll
        for (int mi = 0; mi < 2; ++mi)
            #pragma unroll
            for (int ni = 0; ni < 4; ++ni) {
                int c = jb + n0w + ni*8 + tg*2;
                float b0 = __ldg(bih + c)     + __ldg(bhh + c);
                float b1 = __ldg(bih + c + 1) + __ldg(bhh + c + 1);
                racc[mi][ni][0] = sigmoidf_(racc[mi][ni][0] + b0);
                racc[mi][ni][1] = sigmoidf_(racc[mi][ni][1] + b1);
                racc[mi][ni][2] = sigmoidf_(racc[mi][ni][2] + b0);
                racc[mi][ni][3] = sigmoidf_(racc[mi][ni][3] + b1);
            }

        // ---- gate n (rows 256:384): ng = tanh(i_n + bi + r*(h_n + bh)) ----
        float nacc[2][4][4];  // h_n accumulation first
        #pragma unroll
        for (int mi = 0; mi < 2; ++mi)
            #pragma unroll
            for (int ni = 0; ni < 4; ++ni)
                #pragma unroll
                for (int r = 0; r < 4; ++r) nacc[mi][ni][r] = 0.f;
        gru_gemm_acc(nacc, Hs, whh_t, 256 + jb, Bs, tid, m0, n0w, gid, tg);
        // t = r*(h_n + bh) stored back into racc (r dead after)
        #pragma unroll
        for (int mi = 0; mi < 2; ++mi)
            #pragma unroll
            for (int ni = 0; ni < 4; ++ni) {
                int c = jb + n0w + ni*8 + tg*2;
                float b0 = __ldg(bhh + 256 + c);
                float b1 = __ldg(bhh + 256 + c + 1);
                racc[mi][ni][0] = racc[mi][ni][0]*(nacc[mi][ni][0] + b0);
                racc[mi][ni][1] = racc[mi][ni][1]*(nacc[mi][ni][1] + b1);
                racc[mi][ni][2] = racc[mi][ni][2]*(nacc[mi][ni][2] + b0);
                racc[mi][ni][3] = racc[mi][ni][3]*(nacc[mi][ni][3] + b1);
                #pragma unroll
                for (int r = 0; r < 4; ++r) nacc[mi][ni][r] = 0.f;
            }
        gru_gemm_acc(nacc, Ms, wih_t, 256 + jb, Bs, tid, m0, n0w, gid, tg);
        // ng -> nacc
        #pragma unroll
        for (int mi = 0; mi < 2; ++mi)
            #pragma unroll
            for (int ni = 0; ni < 4; ++ni) {
                int c = jb + n0w + ni*8 + tg*2;
                float b0 = __ldg(bih + 256 + c);
                float b1 = __ldg(bih + 256 + c + 1);
                nacc[mi][ni][0] = tanhf(nacc[mi][ni][0] + b0 + racc[mi][ni][0]);
                nacc[mi][ni][1] = tanhf(nacc[mi][ni][1] + b1 + racc[mi][ni][1]);
                nacc[mi][ni][2] = tanhf(nacc[mi][ni][2] + b0 + racc[mi][ni][2]);
                nacc[mi][ni][3] = tanhf(nacc[mi][ni][3] + b1 + racc[mi][ni][3]);
            }

        // ---- gate z (rows 128:256) + output (racc reused as z acc) ----
        #pragma unroll
        for (int mi = 0; mi < 2; ++mi)
            #pragma unroll
            for (int ni = 0; ni < 4; ++ni)
                #pragma unroll
                for (int r = 0; r < 4; ++r) racc[mi][ni][r] = 0.f;
        gru_gemm_acc(racc, Ms, wih_t, 128 + jb, Bs, tid, m0, n0w, gid, tg);
        gru_gemm_acc(racc, Hs, whh_t, 128 + jb, Bs, tid, m0, n0w, gid, tg);
        #pragma unroll
        for (int mi = 0; mi < 2; ++mi) {
            int r1 = m0 + mi*16 + gid;
            int r2 = r1 + 8;
            int n1 = nbase + r1, n2 = nbase + r2;
            #pragma unroll
            for (int ni = 0; ni < 4; ++ni) {
                int c = jb + n0w + ni*8 + tg*2;
                float b0 = __ldg(bih + 128 + c)     + __ldg(bhh + 128 + c);
                float b1 = __ldg(bih + 128 + c + 1) + __ldg(bhh + 128 + c + 1);
                if (n1 < NN) {
                    float2 hv = *(const float2*)(hx + (size_t)n1*HH + c);
                    float z0 = sigmoidf_(racc[mi][ni][0] + b0);
                    float z1 = sigmoidf_(racc[mi][ni][1] + b1);
                    float2 o;
                    o.x = (1.f - z0)*nacc[mi][ni][0] + z0*hv.x;
                    o.y = (1.f - z1)*nacc[mi][ni][1] + z1*hv.y;
                    *(float2*)(out + (size_t)n1*HH + c) = o;
                }
                if (n2 < NN) {
                    float2 hv = *(const float2*)(hx + (size_t)n2*HH + c);
                    float z0 = sigmoidf_(racc[mi][ni][2] + b0);
                    float z1 = sigmoidf_(racc[mi][ni][3] + b1);
                    float2 o;
                    o.x = (1.f - z0)*nacc[mi][ni][2] + z0*hv.x;
                    o.y = (1.f - z1)*nacc[mi][ni][3] + z1*hv.y;
                    *(float2*)(out + (size_t)n2*HH + c) = o;
                }
            }
        }
    }
}

// ---------------- launcher ----------------
extern "C" void kernel_launch(void* const* d_in, const int* in_sizes, int n_in,
                              void* d_out, int out_size)
{
    const float* hx  = (const float*)d_in[0];
    const int*   ei  = (const int*)d_in[1];
    const int*   et  = (const int*)d_in[2];
    const float* ea  = (const float*)d_in[3];
    const float* W1  = (const float*)d_in[4];
    const float* b1  = (const float*)d_in[5];
    const float* W2  = (const float*)d_in[6];
    const float* b2  = (const float*)d_in[7];
    const float* wih = (const float*)d_in[8];
    const float* whh = (const float*)d_in[9];
    const float* bih = (const float*)d_in[10];
    const float* bhh = (const float*)d_in[11];
    float* out = (float*)d_out;

    cudaFuncSetAttribute(edge_mma_kernel, cudaFuncAttributeMaxDynamicSharedMemorySize, EDGE_DYN_BYTES);
    cudaFuncSetAttribute(gru_mma_kernel, cudaFuncAttributeMaxDynamicSharedMemorySize, GRU_DYN_BYTES);

    zero_counts_kernel<<<1, 32>>>();
    zero_msg_kernel<<<2048, 256>>>();
    fill_sorted_kernel<<<1024, 256>>>();
    hist_kernel<<<800, 256>>>(et);
    scan_kernel<<<1, 32>>>();
    scatter_kernel<<<800, 256>>>(et);
    transpose_w_kernel<<<192, 256>>>(wih, whh);
    round_weights_kernel<<<256, 256>>>(W1, W2);

    edge_mma_kernel<<<SORT_CAP/128, 256, EDGE_DYN_BYTES>>>(hx, ei, et, ea, b1, b2);
    gru_mma_kernel<<<(NN + 127)/128, 256, GRU_DYN_BYTES>>>(hx, bih, bhh, out);
}